// round 15
// baseline (speedup 1.0000x reference)
#include <cuda_runtime.h>
#include <cuda_bf16.h>
#include <math.h>
#include <stdint.h>

#define Bsz 256
#define Slen 128
#define Fdim 128
#define Hdim 512
#define Cdim 64
#define Ldim 16
#define KTOT 640
#define G4 2048
#define NCH 5             // K chunks of 128 (4 h-chunks + 1 x-chunk)

#define ROWB 272          // smem row stride bytes (128 bf16 = 256B + 16B pad)
#define AHALF (64 * ROWB) // 17408
#define BUFB  (4 * AHALF) // 69632 (A hi, A lo, B hi, B lo)
#define NBUF 2
#define SMEM_STEP (NBUF * BUFB)   // 139264
#define CST 68

// -------- device globals (no runtime allocation allowed) --------
__device__ __align__(16) __nv_bfloat16 g_Wh[G4 * KTOT];  // W^T, n'=hcol*4+gate
__device__ __align__(16) __nv_bfloat16 g_Wl[G4 * KTOT];
__device__ __align__(16) __nv_bfloat16 g_xh[Bsz * Slen * Fdim];
__device__ __align__(16) __nv_bfloat16 g_xl[Bsz * Slen * Fdim];
__device__ __align__(16) __nv_bfloat16 g_hh[2][Bsz * Hdim];
__device__ __align__(16) __nv_bfloat16 g_hl[2][Bsz * Hdim];
__device__ float g_c[Bsz * Hdim];
__device__ __align__(16) float g_bsum[G4];
__device__ float g_tmp[Bsz * Hdim];
__device__ float g_ctx[Bsz * 3 * Hdim];

__device__ __forceinline__ uint32_t smem_u32(const void* p) {
    uint32_t a;
    asm("{ .reg .u64 t; cvta.to.shared.u64 t, %1; cvt.u32.u64 %0, t; }" : "=r"(a) : "l"(p));
    return a;
}
__device__ __forceinline__ void cp16(uint32_t sdst, const void* gsrc) {
    asm volatile("cp.async.cg.shared.global [%0], [%1], 16;" :: "r"(sdst), "l"(gsrc));
}
#define CP_COMMIT() asm volatile("cp.async.commit_group;" ::: "memory")
#define CP_WAIT(n)  asm volatile("cp.async.wait_group %0;" :: "n"(n) : "memory")

__device__ __forceinline__ void ldsm_x4(uint32_t addr, uint32_t r[4]) {
    asm volatile("ldmatrix.sync.aligned.m8n8.x4.shared.b16 {%0,%1,%2,%3}, [%4];"
                 : "=r"(r[0]), "=r"(r[1]), "=r"(r[2]), "=r"(r[3]) : "r"(addr));
}
__device__ __forceinline__ void mma16816(float c[4], const uint32_t a[4], const uint32_t b[2]) {
    asm volatile(
        "mma.sync.aligned.m16n8k16.row.col.f32.bf16.bf16.f32 "
        "{%0,%1,%2,%3}, {%4,%5,%6,%7}, {%8,%9}, {%0,%1,%2,%3};"
        : "+f"(c[0]), "+f"(c[1]), "+f"(c[2]), "+f"(c[3])
        : "r"(a[0]), "r"(a[1]), "r"(a[2]), "r"(a[3]), "r"(b[0]), "r"(b[1]));
}
__device__ __forceinline__ float sigf(float x) {
    return __fdividef(1.0f, 1.0f + __expf(-x));
}
__device__ __forceinline__ float tanh_fast(float x) {
    float xc = fminf(fmaxf(x, -15.0f), 15.0f);
    float e = __expf(2.0f * xc);
    return __fdividef(e - 1.0f, e + 1.0f);
}

// ------------------------- prep kernels -------------------------
__global__ __launch_bounds__(256) void prep_kernel(
    const float* __restrict__ b_ih, const float* __restrict__ b_hh)
{
    int i = blockIdx.x * 256 + threadIdx.x;
    if (i < Bsz * Hdim) {
        g_c[i] = 0.0f;
        g_hh[0][i] = __float2bfloat16(0.0f);
        g_hl[0][i] = __float2bfloat16(0.0f);
    }
    if (i < G4) {
        int n = (i & 3) * Hdim + (i >> 2);
        g_bsum[i] = b_ih[n] + b_hh[n];
    }
}
__global__ __launch_bounds__(256) void split_w_kernel(
    const float* __restrict__ W_ih, const float* __restrict__ W_hh)
{
    int idx = blockIdx.x * 256 + threadIdx.x;
    if (idx >= G4 * KTOT) return;
    int np = idx / KTOT, k = idx - np * KTOT;
    int n = (np & 3) * Hdim + (np >> 2);
    float v = (k < Hdim) ? W_hh[k * G4 + n] : W_ih[(k - Hdim) * G4 + n];
    __nv_bfloat16 hi = __float2bfloat16(v);
    g_Wh[idx] = hi;
    g_Wl[idx] = __float2bfloat16(v - __bfloat162float(hi));
}
__global__ __launch_bounds__(256) void split_x_kernel(const float* __restrict__ x) {
    int i = blockIdx.x * 256 + threadIdx.x;
    if (i >= Bsz * Slen * Fdim) return;
    float v = x[i];
    __nv_bfloat16 hi = __float2bfloat16(v);
    g_xh[i] = hi;
    g_xl[i] = __float2bfloat16(v - __bfloat162float(hi));
}

// ctx stage 1: tmp = relu(context @ cg_w1 + cg_b1)  [256,512]
__global__ __launch_bounds__(256) void ctx1_kernel(
    const float* __restrict__ context, const float* __restrict__ cg_w1,
    const float* __restrict__ cg_b1)
{
    __shared__ float cr[16][Cdim];
    const int tid = threadIdx.x;
    const int r0 = blockIdx.y * 16;
    const int c0 = blockIdx.x * 128 + (tid & 63) * 2;
    const int rg = tid >> 6;
    for (int i = tid; i < 16 * Cdim; i += 256)
        cr[i >> 6][i & 63] = context[(r0 + (i >> 6)) * Cdim + (i & 63)];
    __syncthreads();

    float acc[4][2];
#pragma unroll
    for (int i = 0; i < 4; i++) { acc[i][0] = 0.0f; acc[i][1] = 0.0f; }
#pragma unroll 4
    for (int k = 0; k < Cdim; k++) {
        float2 w = *(const float2*)&cg_w1[k * Hdim + c0];
#pragma unroll
        for (int i = 0; i < 4; i++) {
            float a = cr[rg + 4 * i][k];
            acc[i][0] += a * w.x;
            acc[i][1] += a * w.y;
        }
    }
    float2 bb = *(const float2*)&cg_b1[c0];
#pragma unroll
    for (int i = 0; i < 4; i++) {
        int r = r0 + rg + 4 * i;
        g_tmp[r * Hdim + c0]     = fmaxf(acc[i][0] + bb.x, 0.0f);
        g_tmp[r * Hdim + c0 + 1] = fmaxf(acc[i][1] + bb.y, 0.0f);
    }
}

// ctx stage 2: ctx = sigmoid(tmp @ cg_w2 + cg_b2)  [256,1536]
__global__ __launch_bounds__(256) void ctx2_kernel(
    const float* __restrict__ cg_w2, const float* __restrict__ cg_b2)
{
    __shared__ float tr[16][Hdim];
    const int tid = threadIdx.x;
    const int r0 = blockIdx.y * 16;
    const int c0 = blockIdx.x * 128 + (tid & 63) * 2;
    const int rg = tid >> 6;
    for (int i = tid; i < 16 * Hdim; i += 256)
        tr[i >> 9][i & 511] = g_tmp[(r0 + (i >> 9)) * Hdim + (i & 511)];
    __syncthreads();

    float acc[4][2];
#pragma unroll
    for (int i = 0; i < 4; i++) { acc[i][0] = 0.0f; acc[i][1] = 0.0f; }
#pragma unroll 4
    for (int k = 0; k < Hdim; k++) {
        float2 w = *(const float2*)&cg_w2[k * 1536 + c0];
#pragma unroll
        for (int i = 0; i < 4; i++) {
            float a = tr[rg + 4 * i][k];
            acc[i][0] += a * w.x;
            acc[i][1] += a * w.y;
        }
    }
    float2 bb = *(const float2*)&cg_b2[c0];
#pragma unroll
    for (int i = 0; i < 4; i++) {
        int r = r0 + rg + 4 * i;
        g_ctx[r * 1536 + c0]     = 1.0f / (1.0f + expf(-(acc[i][0] + bb.x)));
        g_ctx[r * 1536 + c0 + 1] = 1.0f / (1.0f + expf(-(acc[i][1] + bb.y)));
    }
}

// ------------------- HMMA LSTM step: chunk=128, 2 buffers, 6 barriers ------
// grid (32, 4) = 128 CTAs, 256 threads = 8 warps (4 M x 2 N), warp M16 x N32.
__global__ __launch_bounds__(256) void step_kernel(int t)
{
    extern __shared__ char smem[];
    const uint32_t sb = smem_u32(smem);
    const int tid = threadIdx.x;
    const int wid = tid >> 5, lane = tid & 31;
    const int wm = wid & 3, wn = wid >> 2;
    const int gID = lane >> 2, tid4 = lane & 3;
    const int n0 = blockIdx.x * 64;
    const int hcol0 = blockIdx.x * 16;
    const int b0 = blockIdx.y * 64;

    const __nv_bfloat16* __restrict__ hh = g_hh[t & 1];
    const __nv_bfloat16* __restrict__ hl = g_hl[t & 1];
    __nv_bfloat16* __restrict__ ohh = g_hh[(t + 1) & 1];
    __nv_bfloat16* __restrict__ ohl = g_hl[(t + 1) & 1];

    float acc[4][4];
#pragma unroll
    for (int j = 0; j < 4; j++)
#pragma unroll
        for (int r = 0; r < 4; r++) acc[j][r] = 0.0f;

    const uint32_t aOff = (uint32_t)((wm * 16 + (lane & 15)) * ROWB + ((lane >> 4) * 16));
    const uint32_t bOff0 = (uint32_t)((wn * 32 + ((lane >> 4) & 1) * 8 + (lane & 7)) * ROWB
                                      + (((lane >> 3) & 1) * 16));

    // copy one K=128 chunk (A hi/lo + B hi/lo), 16 cp16 per thread
    auto copyc = [&](int c) {
        const uint32_t base = sb + (uint32_t)(c & 1) * BUFB;
#pragma unroll
        for (int half = 0; half < 2; half++) {
#pragma unroll
            for (int i = 0; i < 4; i++) {
                int idx = i * 256 + tid, r = idx >> 4, q = idx & 15;
                uint32_t dst = base + half * AHALF + r * ROWB + q * 16;
                if (c < 4) {
                    const __nv_bfloat16* src = half ? hl : hh;
                    cp16(dst, src + (size_t)(b0 + r) * Hdim + c * 128 + q * 8);
                } else {
                    const __nv_bfloat16* src = half ? g_xl : g_xh;
                    cp16(dst, src + ((size_t)(b0 + r) * Slen + t) * Fdim + q * 8);
                }
            }
        }
#pragma unroll
        for (int half = 0; half < 2; half++) {
#pragma unroll
            for (int i = 0; i < 4; i++) {
                int idx = i * 256 + tid, r = idx >> 4, q = idx & 15;
                cp16(base + 2 * AHALF + half * AHALF + r * ROWB + q * 16,
                     (half ? g_Wl : g_Wh) + (size_t)(n0 + r) * KTOT + c * 128 + q * 8);
            }
        }
    };

    auto computec = [&](int c) {
        const uint32_t base = sb + (uint32_t)(c & 1) * BUFB;
        const uint32_t aAddr = base + aOff;
        const uint32_t bAddr = base + 2 * AHALF + bOff0;
#pragma unroll
        for (int ks = 0; ks < 8; ks++) {
            const uint32_t kb = ks * 32;
            uint32_t aH[4], aL[4];
            ldsm_x4(aAddr + kb, aH);
            ldsm_x4(aAddr + kb + AHALF, aL);
#pragma unroll
            for (int p = 0; p < 2; p++) {
                uint32_t bh[4], bl[4];
                ldsm_x4(bAddr + p * (16 * ROWB) + kb, bh);
                ldsm_x4(bAddr + p * (16 * ROWB) + kb + AHALF, bl);
                mma16816(acc[p * 2 + 0], aH, bh + 0);
                mma16816(acc[p * 2 + 0], aH, bl + 0);
                mma16816(acc[p * 2 + 0], aL, bh + 0);
                mma16816(acc[p * 2 + 1], aH, bh + 2);
                mma16816(acc[p * 2 + 1], aH, bl + 2);
                mma16816(acc[p * 2 + 1], aL, bh + 2);
            }
        }
    };

    copyc(0); CP_COMMIT();
#pragma unroll 1
    for (int c = 0; c < NCH; c++) {
        CP_WAIT(0);           // chunk c landed (copy c+1 not yet issued)
        __syncthreads();      // all warps past compute(c-1): buf (c+1)&1 free
        if (c + 1 < NCH) { copyc(c + 1); CP_COMMIT(); }  // hides under compute(c)
        computec(c);
    }

    // ---- epilogue: acc -> Csm (buf1; last chunk read buf0) -> LSTM update --
    float* Csm = (float*)(smem + BUFB);   // 64 x CST floats = 17408 B <= BUFB
#pragma unroll
    for (int j = 0; j < 4; j++) {
        int n = wn * 32 + j * 8 + tid4 * 2;
        int m0r = wm * 16 + gID;
        *(float2*)&Csm[m0r * CST + n]       = make_float2(acc[j][0], acc[j][1]);
        *(float2*)&Csm[(m0r + 8) * CST + n] = make_float2(acc[j][2], acc[j][3]);
    }
    __syncthreads();
#pragma unroll
    for (int it = 0; it < 4; it++) {
        int idx = it * 256 + tid;
        int m = idx >> 4, hcl = idx & 15;
        float4 gv = *(float4*)&Csm[m * CST + hcl * 4];
        float4 bb = *(const float4*)&g_bsum[n0 + hcl * 4];
        int b = b0 + m, hc = hcol0 + hcl;
        const float* cxp = g_ctx + (size_t)b * 1536;
        float iv = sigf(gv.x + bb.x) * cxp[hc];
        float fv = sigf(gv.y + bb.y) * cxp[Hdim + hc];
        float gg = tanh_fast(gv.z + bb.z);
        float ov = sigf(gv.w + bb.w) * cxp[2 * Hdim + hc];
        float cn = fv * g_c[(size_t)b * Hdim + hc] + iv * gg;
        g_c[(size_t)b * Hdim + hc] = cn;
        float hv = ov * tanh_fast(cn);
        __nv_bfloat16 hhi = __float2bfloat16(hv);
        ohh[(size_t)b * Hdim + hc] = hhi;
        ohl[(size_t)b * Hdim + hc] = __float2bfloat16(hv - __bfloat162float(hhi));
    }
}

// ------------------------- VAE head -------------------------
__global__ __launch_bounds__(128) void head_kernel(
    const float* __restrict__ eps,
    const float* __restrict__ mu_w, const float* __restrict__ mu_b,
    const float* __restrict__ lv_w, const float* __restrict__ lv_b,
    const float* __restrict__ dec_w1, const float* __restrict__ dec_b1,
    const float* __restrict__ dec_w2, const float* __restrict__ dec_b2,
    float* __restrict__ out)
{
    __shared__ float hrow[Hdim];
    __shared__ float zv[Ldim];
    __shared__ float d1[Hdim];
    int b = blockIdx.x;

    for (int k = threadIdx.x; k < Hdim; k += 128)
        hrow[k] = __bfloat162float(g_hh[0][(size_t)b * Hdim + k]) +
                  __bfloat162float(g_hl[0][(size_t)b * Hdim + k]);
    __syncthreads();

    if (threadIdx.x < Ldim) {
        int j = threadIdx.x;
        float m = mu_b[j];
        for (int k = 0; k < Hdim; k++) m += hrow[k] * mu_w[k * Ldim + j];
        out[Bsz * Fdim + b * Ldim + j] = m;
        float lv = lv_b[j];
        for (int k = 0; k < Hdim; k++) lv += hrow[k] * lv_w[k * Ldim + j];
        out[Bsz * Fdim + Bsz * Ldim + b * Ldim + j] = lv;
        zv[j] = m + eps[b * Ldim + j] * expf(0.5f * lv);
    }
    __syncthreads();

    for (int n = threadIdx.x; n < Hdim; n += 128) {
        float s = dec_b1[n];
#pragma unroll
        for (int k = 0; k < Ldim; k++) s += zv[k] * dec_w1[k * Hdim + n];
        d1[n] = fmaxf(s, 0.0f);
    }
    __syncthreads();
    {
        int n = threadIdx.x;
        float s = dec_b2[n];
        for (int k = 0; k < Hdim; k++) s += d1[k] * dec_w2[k * Fdim + n];
        out[(size_t)b * Fdim + n] = s;
    }
}

// ---------------------------------------------------------------------------
extern "C" void kernel_launch(void* const* d_in, const int* in_sizes, int n_in,
                              void* d_out, int out_size)
{
    const float* x       = (const float*)d_in[0];
    const float* context = (const float*)d_in[1];
    const float* eps     = (const float*)d_in[2];
    const float* W_ih    = (const float*)d_in[3];
    const float* b_ih    = (const float*)d_in[4];
    const float* W_hh    = (const float*)d_in[5];
    const float* b_hh    = (const float*)d_in[6];
    const float* cg_w1   = (const float*)d_in[7];
    const float* cg_b1   = (const float*)d_in[8];
    const float* cg_w2   = (const float*)d_in[9];
    const float* cg_b2   = (const float*)d_in[10];
    const float* mu_w    = (const float*)d_in[11];
    const float* mu_b    = (const float*)d_in[12];
    const float* lv_w    = (const float*)d_in[13];
    const float* lv_b    = (const float*)d_in[14];
    const float* dec_w1  = (const float*)d_in[15];
    const float* dec_b1  = (const float*)d_in[16];
    const float* dec_w2  = (const float*)d_in[17];
    const float* dec_b2  = (const float*)d_in[18];
    float* out = (float*)d_out;

    cudaFuncSetAttribute(step_kernel, cudaFuncAttributeMaxDynamicSharedMemorySize,
                         SMEM_STEP);

    prep_kernel<<<(Bsz * Hdim + 255) / 256, 256>>>(b_ih, b_hh);
    split_w_kernel<<<(G4 * KTOT + 255) / 256, 256>>>(W_ih, W_hh);
    split_x_kernel<<<(Bsz * Slen * Fdim + 255) / 256, 256>>>(x);
    ctx1_kernel<<<dim3(4, 16), 256>>>(context, cg_w1, cg_b1);
    ctx2_kernel<<<dim3(12, 16), 256>>>(cg_w2, cg_b2);

    for (int t = 0; t < Slen; t++) {
        step_kernel<<<dim3(32, 4), 256, SMEM_STEP>>>(t);
    }

    head_kernel<<<Bsz, 128>>>(eps, mu_w, mu_b, lv_w, lv_b,
                              dec_w1, dec_b1, dec_w2, dec_b2, out);
}

// round 16
// speedup vs baseline: 1.0180x; 1.0180x over previous
#include <cuda_runtime.h>
#include <cuda_bf16.h>
#include <math.h>
#include <stdint.h>

#define Bsz 256
#define Slen 128
#define Fdim 128
#define Hdim 512
#define Cdim 64
#define Ldim 16
#define KTOT 640
#define G4 2048
#define NCH 10            // K chunks of 64

#define ROWB 144          // smem row stride bytes (64 bf16 = 128B + 16B pad)
#define AHALF (64 * ROWB) // 9216
#define BUFB  (4 * AHALF) // 36864 (A hi, A lo, B hi, B lo)
#define NBUF 4
#define SMEM_STEP (NBUF * BUFB)   // 147456
#define CST 68

// -------- device globals (no runtime allocation allowed) --------
__device__ __align__(16) __nv_bfloat16 g_Wh[G4 * KTOT];  // W^T, n'=hcol*4+gate
__device__ __align__(16) __nv_bfloat16 g_Wl[G4 * KTOT];
__device__ __align__(16) __nv_bfloat16 g_xh[Bsz * Slen * Fdim];
__device__ __align__(16) __nv_bfloat16 g_xl[Bsz * Slen * Fdim];
__device__ __align__(16) __nv_bfloat16 g_hh[2][Bsz * Hdim];
__device__ __align__(16) __nv_bfloat16 g_hl[2][Bsz * Hdim];
__device__ float g_c[Bsz * Hdim];
__device__ __align__(16) float g_bsum[G4];
__device__ float g_tmp[Bsz * Hdim];
__device__ float g_ctx[Bsz * 3 * Hdim];

__device__ __forceinline__ uint32_t smem_u32(const void* p) {
    uint32_t a;
    asm("{ .reg .u64 t; cvta.to.shared.u64 t, %1; cvt.u32.u64 %0, t; }" : "=r"(a) : "l"(p));
    return a;
}
__device__ __forceinline__ void cp16(uint32_t sdst, const void* gsrc) {
    asm volatile("cp.async.cg.shared.global [%0], [%1], 16;" :: "r"(sdst), "l"(gsrc));
}
#define CP_COMMIT() asm volatile("cp.async.commit_group;" ::: "memory")
#define CP_WAIT(n)  asm volatile("cp.async.wait_group %0;" :: "n"(n) : "memory")

__device__ __forceinline__ void ldsm_x4(uint32_t addr, uint32_t r[4]) {
    asm volatile("ldmatrix.sync.aligned.m8n8.x4.shared.b16 {%0,%1,%2,%3}, [%4];"
                 : "=r"(r[0]), "=r"(r[1]), "=r"(r[2]), "=r"(r[3]) : "r"(addr));
}
__device__ __forceinline__ void mma16816(float c[4], const uint32_t a[4], const uint32_t b[2]) {
    asm volatile(
        "mma.sync.aligned.m16n8k16.row.col.f32.bf16.bf16.f32 "
        "{%0,%1,%2,%3}, {%4,%5,%6,%7}, {%8,%9}, {%0,%1,%2,%3};"
        : "+f"(c[0]), "+f"(c[1]), "+f"(c[2]), "+f"(c[3])
        : "r"(a[0]), "r"(a[1]), "r"(a[2]), "r"(a[3]), "r"(b[0]), "r"(b[1]));
}
__device__ __forceinline__ float sigf(float x) {
    return __fdividef(1.0f, 1.0f + __expf(-x));
}
__device__ __forceinline__ float tanh_fast(float x) {
    float xc = fminf(fmaxf(x, -15.0f), 15.0f);
    float e = __expf(2.0f * xc);
    return __fdividef(e - 1.0f, e + 1.0f);
}

// ------------------------- prep kernels -------------------------
__global__ __launch_bounds__(256) void prep_kernel(
    const float* __restrict__ b_ih, const float* __restrict__ b_hh)
{
    int i = blockIdx.x * 256 + threadIdx.x;
    if (i < Bsz * Hdim) {
        g_c[i] = 0.0f;
        g_hh[0][i] = __float2bfloat16(0.0f);
        g_hl[0][i] = __float2bfloat16(0.0f);
    }
    if (i < G4) {
        int n = (i & 3) * Hdim + (i >> 2);
        g_bsum[i] = b_ih[n] + b_hh[n];
    }
}
__global__ __launch_bounds__(256) void split_w_kernel(
    const float* __restrict__ W_ih, const float* __restrict__ W_hh)
{
    int idx = blockIdx.x * 256 + threadIdx.x;
    if (idx >= G4 * KTOT) return;
    int np = idx / KTOT, k = idx - np * KTOT;
    int n = (np & 3) * Hdim + (np >> 2);
    float v = (k < Hdim) ? W_hh[k * G4 + n] : W_ih[(k - Hdim) * G4 + n];
    __nv_bfloat16 hi = __float2bfloat16(v);
    g_Wh[idx] = hi;
    g_Wl[idx] = __float2bfloat16(v - __bfloat162float(hi));
}
// vectorized x split: float4 in, packed 4xbf16 (uint2) out per array
__global__ __launch_bounds__(256) void split_x_kernel(const float* __restrict__ x) {
    int i = (blockIdx.x * 256 + threadIdx.x) * 4;
    if (i >= Bsz * Slen * Fdim) return;
    float4 v = *(const float4*)&x[i];
    __nv_bfloat16 h0 = __float2bfloat16(v.x);
    __nv_bfloat16 h1 = __float2bfloat16(v.y);
    __nv_bfloat16 h2 = __float2bfloat16(v.z);
    __nv_bfloat16 h3 = __float2bfloat16(v.w);
    __nv_bfloat16 l0 = __float2bfloat16(v.x - __bfloat162float(h0));
    __nv_bfloat16 l1 = __float2bfloat16(v.y - __bfloat162float(h1));
    __nv_bfloat16 l2 = __float2bfloat16(v.z - __bfloat162float(h2));
    __nv_bfloat16 l3 = __float2bfloat16(v.w - __bfloat162float(h3));
    uint2 ph, pl;
    ph.x = (uint32_t)__bfloat16_as_ushort(h0) | ((uint32_t)__bfloat16_as_ushort(h1) << 16);
    ph.y = (uint32_t)__bfloat16_as_ushort(h2) | ((uint32_t)__bfloat16_as_ushort(h3) << 16);
    pl.x = (uint32_t)__bfloat16_as_ushort(l0) | ((uint32_t)__bfloat16_as_ushort(l1) << 16);
    pl.y = (uint32_t)__bfloat16_as_ushort(l2) | ((uint32_t)__bfloat16_as_ushort(l3) << 16);
    *(uint2*)&g_xh[i] = ph;
    *(uint2*)&g_xl[i] = pl;
}

// ctx stage 1: tmp = relu(context @ cg_w1 + cg_b1)  [256,512]
// grid (4, 32): bx = 128-col tile, by = 8-row tile; thread = 1 row x 4 cols.
__global__ __launch_bounds__(256) void ctx1_kernel(
    const float* __restrict__ context, const float* __restrict__ cg_w1,
    const float* __restrict__ cg_b1)
{
    __shared__ float cr[8][Cdim];
    const int tid = threadIdx.x;
    const int r0 = blockIdx.y * 8;
    const int row = tid >> 5;
    const int c0 = blockIdx.x * 128 + (tid & 31) * 4;
    for (int i = tid; i < 8 * Cdim; i += 256)
        cr[i >> 6][i & 63] = context[(r0 + (i >> 6)) * Cdim + (i & 63)];
    __syncthreads();

    float4 acc = make_float4(0.f, 0.f, 0.f, 0.f);
#pragma unroll 4
    for (int k = 0; k < Cdim; k++) {
        float4 w = *(const float4*)&cg_w1[k * Hdim + c0];
        float a = cr[row][k];
        acc.x += a * w.x; acc.y += a * w.y;
        acc.z += a * w.z; acc.w += a * w.w;
    }
    float4 bb = *(const float4*)&cg_b1[c0];
    float4 o;
    o.x = fmaxf(acc.x + bb.x, 0.0f);
    o.y = fmaxf(acc.y + bb.y, 0.0f);
    o.z = fmaxf(acc.z + bb.z, 0.0f);
    o.w = fmaxf(acc.w + bb.w, 0.0f);
    *(float4*)&g_tmp[(r0 + row) * Hdim + c0] = o;
}

// ctx stage 2: ctx = sigmoid(tmp @ cg_w2 + cg_b2)  [256,1536]
__global__ __launch_bounds__(256) void ctx2_kernel(
    const float* __restrict__ cg_w2, const float* __restrict__ cg_b2)
{
    __shared__ float tr[16][Hdim];
    const int tid = threadIdx.x;
    const int r0 = blockIdx.y * 16;
    const int c0 = blockIdx.x * 128 + (tid & 63) * 2;
    const int rg = tid >> 6;
    for (int i = tid; i < 16 * Hdim; i += 256)
        tr[i >> 9][i & 511] = g_tmp[(r0 + (i >> 9)) * Hdim + (i & 511)];
    __syncthreads();

    float acc[4][2];
#pragma unroll
    for (int i = 0; i < 4; i++) { acc[i][0] = 0.0f; acc[i][1] = 0.0f; }
#pragma unroll 4
    for (int k = 0; k < Hdim; k++) {
        float2 w = *(const float2*)&cg_w2[k * 1536 + c0];
#pragma unroll
        for (int i = 0; i < 4; i++) {
            float a = tr[rg + 4 * i][k];
            acc[i][0] += a * w.x;
            acc[i][1] += a * w.y;
        }
    }
    float2 bb = *(const float2*)&cg_b2[c0];
#pragma unroll
    for (int i = 0; i < 4; i++) {
        int r = r0 + rg + 4 * i;
        g_ctx[r * 1536 + c0]     = 1.0f / (1.0f + expf(-(acc[i][0] + bb.x)));
        g_ctx[r * 1536 + c0 + 1] = 1.0f / (1.0f + expf(-(acc[i][1] + bb.y)));
    }
}

// ------------------- HMMA LSTM step (R14-proven: ldmatrix + 4buf + Csm) ----
// grid (32, 4) = 128 CTAs, 256 threads = 8 warps (4 M x 2 N), warp M16 x N32.
__global__ __launch_bounds__(256) void step_kernel(int t)
{
    extern __shared__ char smem[];
    const uint32_t sb = smem_u32(smem);
    const int tid = threadIdx.x;
    const int wid = tid >> 5, lane = tid & 31;
    const int wm = wid & 3, wn = wid >> 2;
    const int gID = lane >> 2, tid4 = lane & 3;
    const int n0 = blockIdx.x * 64;
    const int hcol0 = blockIdx.x * 16;
    const int b0 = blockIdx.y * 64;

    const __nv_bfloat16* __restrict__ hh = g_hh[t & 1];
    const __nv_bfloat16* __restrict__ hl = g_hl[t & 1];
    __nv_bfloat16* __restrict__ ohh = g_hh[(t + 1) & 1];
    __nv_bfloat16* __restrict__ ohl = g_hl[(t + 1) & 1];

    float acc[4][4];
#pragma unroll
    for (int j = 0; j < 4; j++)
#pragma unroll
        for (int r = 0; r < 4; r++) acc[j][r] = 0.0f;

    const uint32_t aOff = (uint32_t)((wm * 16 + (lane & 15)) * ROWB + ((lane >> 4) * 16));
    const uint32_t bOff0 = (uint32_t)((wn * 32 + ((lane >> 4) & 1) * 8 + (lane & 7)) * ROWB
                                      + (((lane >> 3) & 1) * 16));

    auto copyc = [&](int c) {
        const uint32_t base = sb + (uint32_t)(c % NBUF) * BUFB;
#pragma unroll
        for (int half = 0; half < 2; half++) {
#pragma unroll
            for (int i = 0; i < 2; i++) {
                int idx = i * 256 + tid, r = idx >> 3, q = idx & 7;
                uint32_t dst = base + half * AHALF + r * ROWB + q * 16;
                if (c < 8) {
                    const __nv_bfloat16* src = half ? hl : hh;
                    cp16(dst, src + (size_t)(b0 + r) * Hdim + c * 64 + q * 8);
                } else {
                    const __nv_bfloat16* src = half ? g_xl : g_xh;
                    cp16(dst, src + ((size_t)(b0 + r) * Slen + t) * Fdim + (c - 8) * 64 + q * 8);
                }
            }
        }
#pragma unroll
        for (int half = 0; half < 2; half++) {
#pragma unroll
            for (int i = 0; i < 2; i++) {
                int idx = i * 256 + tid, r = idx >> 3, q = idx & 7;
                cp16(base + 2 * AHALF + half * AHALF + r * ROWB + q * 16,
                     (half ? g_Wl : g_Wh) + (size_t)(n0 + r) * KTOT + c * 64 + q * 8);
            }
        }
    };

    auto computec = [&](int c) {
        const uint32_t base = sb + (uint32_t)(c % NBUF) * BUFB;
        const uint32_t aAddr = base + aOff;
        const uint32_t bAddr = base + 2 * AHALF + bOff0;
#pragma unroll
        for (int ks = 0; ks < 4; ks++) {
            const uint32_t kb = ks * 32;
            uint32_t aH[4], aL[4];
            ldsm_x4(aAddr + kb, aH);
            ldsm_x4(aAddr + kb + AHALF, aL);
#pragma unroll
            for (int p = 0; p < 2; p++) {
                uint32_t bh[4], bl[4];
                ldsm_x4(bAddr + p * (16 * ROWB) + kb, bh);
                ldsm_x4(bAddr + p * (16 * ROWB) + kb + AHALF, bl);
                mma16816(acc[p * 2 + 0], aH, bh + 0);
                mma16816(acc[p * 2 + 0], aH, bl + 0);
                mma16816(acc[p * 2 + 0], aL, bh + 0);
                mma16816(acc[p * 2 + 1], aH, bh + 2);
                mma16816(acc[p * 2 + 1], aH, bl + 2);
                mma16816(acc[p * 2 + 1], aL, bh + 2);
            }
        }
    };

    copyc(0); CP_COMMIT();
    copyc(1); CP_COMMIT();
#pragma unroll 1
    for (int c = 0; c < NCH; c++) {
        if (c + 2 < NCH) { copyc(c + 2); CP_COMMIT(); }
        if (c + 2 < NCH)      { CP_WAIT(2); }
        else if (c + 1 < NCH) { CP_WAIT(1); }
        else                  { CP_WAIT(0); }
        __syncthreads();          // single barrier per chunk (NBUF=4 disjointness)
        computec(c);
    }

    // ---- epilogue: acc -> Csm -> fused LSTM update (coalesced stores) ----
    float* Csm = (float*)smem;   // 64 x CST floats = 17408 B < BUFB
#pragma unroll
    for (int j = 0; j < 4; j++) {
        int n = wn * 32 + j * 8 + tid4 * 2;
        int m0r = wm * 16 + gID;
        *(float2*)&Csm[m0r * CST + n]       = make_float2(acc[j][0], acc[j][1]);
        *(float2*)&Csm[(m0r + 8) * CST + n] = make_float2(acc[j][2], acc[j][3]);
    }
    __syncthreads();
#pragma unroll
    for (int it = 0; it < 4; it++) {
        int idx = it * 256 + tid;
        int m = idx >> 4, hcl = idx & 15;
        float4 gv = *(float4*)&Csm[m * CST + hcl * 4];
        float4 bb = *(const float4*)&g_bsum[n0 + hcl * 4];
        int b = b0 + m, hc = hcol0 + hcl;
        const float* cxp = g_ctx + (size_t)b * 1536;
        float iv = sigf(gv.x + bb.x) * cxp[hc];
        float fv = sigf(gv.y + bb.y) * cxp[Hdim + hc];
        float gg = tanh_fast(gv.z + bb.z);
        float ov = sigf(gv.w + bb.w) * cxp[2 * Hdim + hc];
        float cn = fv * g_c[(size_t)b * Hdim + hc] + iv * gg;
        g_c[(size_t)b * Hdim + hc] = cn;
        float hv = ov * tanh_fast(cn);
        __nv_bfloat16 hhi = __float2bfloat16(hv);
        ohh[(size_t)b * Hdim + hc] = hhi;
        ohl[(size_t)b * Hdim + hc] = __float2bfloat16(hv - __bfloat162float(hhi));
    }
}

// ------------------------- VAE head -------------------------
__global__ __launch_bounds__(128) void head_kernel(
    const float* __restrict__ eps,
    const float* __restrict__ mu_w, const float* __restrict__ mu_b,
    const float* __restrict__ lv_w, const float* __restrict__ lv_b,
    const float* __restrict__ dec_w1, const float* __restrict__ dec_b1,
    const float* __restrict__ dec_w2, const float* __restrict__ dec_b2,
    float* __restrict__ out)
{
    __shared__ float hrow[Hdim];
    __shared__ float zv[Ldim];
    __shared__ float d1[Hdim];
    int b = blockIdx.x;

    for (int k = threadIdx.x; k < Hdim; k += 128)
        hrow[k] = __bfloat162float(g_hh[0][(size_t)b * Hdim + k]) +
                  __bfloat162float(g_hl[0][(size_t)b * Hdim + k]);
    __syncthreads();

    if (threadIdx.x < Ldim) {
        int j = threadIdx.x;
        float m = mu_b[j];
        for (int k = 0; k < Hdim; k++) m += hrow[k] * mu_w[k * Ldim + j];
        out[Bsz * Fdim + b * Ldim + j] = m;
        float lv = lv_b[j];
        for (int k = 0; k < Hdim; k++) lv += hrow[k] * lv_w[k * Ldim + j];
        out[Bsz * Fdim + Bsz * Ldim + b * Ldim + j] = lv;
        zv[j] = m + eps[b * Ldim + j] * expf(0.5f * lv);
    }
    __syncthreads();

    for (int n = threadIdx.x; n < Hdim; n += 128) {
        float s = dec_b1[n];
#pragma unroll
        for (int k = 0; k < Ldim; k++) s += zv[k] * dec_w1[k * Hdim + n];
        d1[n] = fmaxf(s, 0.0f);
    }
    __syncthreads();
    {
        int n = threadIdx.x;
        float s = dec_b2[n];
        for (int k = 0; k < Hdim; k++) s += d1[k] * dec_w2[k * Fdim + n];
        out[(size_t)b * Fdim + n] = s;
    }
}

// ---------------------------------------------------------------------------
extern "C" void kernel_launch(void* const* d_in, const int* in_sizes, int n_in,
                              void* d_out, int out_size)
{
    const float* x       = (const float*)d_in[0];
    const float* context = (const float*)d_in[1];
    const float* eps     = (const float*)d_in[2];
    const float* W_ih    = (const float*)d_in[3];
    const float* b_ih    = (const float*)d_in[4];
    const float* W_hh    = (const float*)d_in[5];
    const float* b_hh    = (const float*)d_in[6];
    const float* cg_w1   = (const float*)d_in[7];
    const float* cg_b1   = (const float*)d_in[8];
    const float* cg_w2   = (const float*)d_in[9];
    const float* cg_b2   = (const float*)d_in[10];
    const float* mu_w    = (const float*)d_in[11];
    const float* mu_b    = (const float*)d_in[12];
    const float* lv_w    = (const float*)d_in[13];
    const float* lv_b    = (const float*)d_in[14];
    const float* dec_w1  = (const float*)d_in[15];
    const float* dec_b1  = (const float*)d_in[16];
    const float* dec_w2  = (const float*)d_in[17];
    const float* dec_b2  = (const float*)d_in[18];
    float* out = (float*)d_out;

    cudaFuncSetAttribute(step_kernel, cudaFuncAttributeMaxDynamicSharedMemorySize,
                         SMEM_STEP);

    prep_kernel<<<(Bsz * Hdim + 255) / 256, 256>>>(b_ih, b_hh);
    split_w_kernel<<<(G4 * KTOT + 255) / 256, 256>>>(W_ih, W_hh);
    split_x_kernel<<<(Bsz * Slen * Fdim / 4 + 255) / 256, 256>>>(x);
    ctx1_kernel<<<dim3(4, 32), 256>>>(context, cg_w1, cg_b1);
    ctx2_kernel<<<dim3(12, 16), 256>>>(cg_w2, cg_b2);

    for (int t = 0; t < Slen; t++) {
        step_kernel<<<dim3(32, 4), 256, SMEM_STEP>>>(t);
    }

    head_kernel<<<Bsz, 128>>>(eps, mu_w, mu_b, lv_w, lv_b,
                              dec_w1, dec_b1, dec_w2, dec_b2, out);
}

// round 17
// speedup vs baseline: 1.1243x; 1.1044x over previous
#include <cuda_runtime.h>
#include <cuda_bf16.h>
#include <math.h>
#include <stdint.h>

#define Bsz 256
#define Slen 128
#define Fdim 128
#define Hdim 512
#define Cdim 64
#define Ldim 16
#define KTOT 640
#define G4 2048
#define NCH 10            // K chunks of 64

// persistent-kernel smem layout
#define WROWB 1296                     // W row stride (640*2 + 16 pad)
#define WHALF (64 * WROWB)             // 82944 per half (hi / lo)
#define AROWB 144                      // A row stride (128B + 16 pad)
#define AHALF (64 * AROWB)             // 9216
#define ABUF  (2 * AHALF)              // 18432 (A hi + A lo)
#define NBUF 2
#define AOFF  (2 * WHALF)              // 165888
#define CTXOFF (AOFF + NBUF * ABUF)    // 202752 (64 rows x 48 floats)
#define BIASOFF (CTXOFF + 12288)       // 215040 (64 floats)
#define SMEM_PERSIST (BIASOFF + 256)   // 215296
#define CST 68

// -------- device globals (no runtime allocation allowed) --------
__device__ __align__(16) __nv_bfloat16 g_Wh[G4 * KTOT];  // W^T, n'=hcol*4+gate
__device__ __align__(16) __nv_bfloat16 g_Wl[G4 * KTOT];
__device__ __align__(16) __nv_bfloat16 g_xh[Bsz * Slen * Fdim];
__device__ __align__(16) __nv_bfloat16 g_xl[Bsz * Slen * Fdim];
__device__ __align__(16) __nv_bfloat16 g_hh[2][Bsz * Hdim];
__device__ __align__(16) __nv_bfloat16 g_hl[2][Bsz * Hdim];
__device__ __align__(16) float g_bsum[G4];
__device__ float g_tmp[Bsz * Hdim];
__device__ float g_ctx[Bsz * 3 * Hdim];
__device__ int g_cntG[4];
__device__ volatile int g_flgG[4];

__device__ __forceinline__ uint32_t smem_u32(const void* p) {
    uint32_t a;
    asm("{ .reg .u64 t; cvta.to.shared.u64 t, %1; cvt.u32.u64 %0, t; }" : "=r"(a) : "l"(p));
    return a;
}
__device__ __forceinline__ void cp16(uint32_t sdst, const void* gsrc) {
    asm volatile("cp.async.cg.shared.global [%0], [%1], 16;" :: "r"(sdst), "l"(gsrc));
}
#define CP_COMMIT() asm volatile("cp.async.commit_group;" ::: "memory")
#define CP_WAIT(n)  asm volatile("cp.async.wait_group %0;" :: "n"(n) : "memory")

__device__ __forceinline__ void ldsm_x4(uint32_t addr, uint32_t r[4]) {
    asm volatile("ldmatrix.sync.aligned.m8n8.x4.shared.b16 {%0,%1,%2,%3}, [%4];"
                 : "=r"(r[0]), "=r"(r[1]), "=r"(r[2]), "=r"(r[3]) : "r"(addr));
}
__device__ __forceinline__ void mma16816(float c[4], const uint32_t a[4], const uint32_t b[2]) {
    asm volatile(
        "mma.sync.aligned.m16n8k16.row.col.f32.bf16.bf16.f32 "
        "{%0,%1,%2,%3}, {%4,%5,%6,%7}, {%8,%9}, {%0,%1,%2,%3};"
        : "+f"(c[0]), "+f"(c[1]), "+f"(c[2]), "+f"(c[3])
        : "r"(a[0]), "r"(a[1]), "r"(a[2]), "r"(a[3]), "r"(b[0]), "r"(b[1]));
}
__device__ __forceinline__ float sigf(float x) {
    return __fdividef(1.0f, 1.0f + __expf(-x));
}
__device__ __forceinline__ float tanh_fast(float x) {
    float xc = fminf(fmaxf(x, -15.0f), 15.0f);
    float e = __expf(2.0f * xc);
    return __fdividef(e - 1.0f, e + 1.0f);
}

// ------------------------- prep kernels (R16-proven) -------------------------
__global__ __launch_bounds__(256) void prep_kernel(
    const float* __restrict__ b_ih, const float* __restrict__ b_hh)
{
    int i = blockIdx.x * 256 + threadIdx.x;
    if (i < Bsz * Hdim) {
        g_hh[0][i] = __float2bfloat16(0.0f);
        g_hl[0][i] = __float2bfloat16(0.0f);
    }
    if (i < G4) {
        int n = (i & 3) * Hdim + (i >> 2);
        g_bsum[i] = b_ih[n] + b_hh[n];
    }
}
__global__ __launch_bounds__(256) void split_w_kernel(
    const float* __restrict__ W_ih, const float* __restrict__ W_hh)
{
    int idx = blockIdx.x * 256 + threadIdx.x;
    if (idx >= G4 * KTOT) return;
    int np = idx / KTOT, k = idx - np * KTOT;
    int n = (np & 3) * Hdim + (np >> 2);
    float v = (k < Hdim) ? W_hh[k * G4 + n] : W_ih[(k - Hdim) * G4 + n];
    __nv_bfloat16 hi = __float2bfloat16(v);
    g_Wh[idx] = hi;
    g_Wl[idx] = __float2bfloat16(v - __bfloat162float(hi));
}
__global__ __launch_bounds__(256) void split_x_kernel(const float* __restrict__ x) {
    int i = (blockIdx.x * 256 + threadIdx.x) * 4;
    if (i >= Bsz * Slen * Fdim) return;
    float4 v = *(const float4*)&x[i];
    __nv_bfloat16 h0 = __float2bfloat16(v.x);
    __nv_bfloat16 h1 = __float2bfloat16(v.y);
    __nv_bfloat16 h2 = __float2bfloat16(v.z);
    __nv_bfloat16 h3 = __float2bfloat16(v.w);
    __nv_bfloat16 l0 = __float2bfloat16(v.x - __bfloat162float(h0));
    __nv_bfloat16 l1 = __float2bfloat16(v.y - __bfloat162float(h1));
    __nv_bfloat16 l2 = __float2bfloat16(v.z - __bfloat162float(h2));
    __nv_bfloat16 l3 = __float2bfloat16(v.w - __bfloat162float(h3));
    uint2 ph, pl;
    ph.x = (uint32_t)__bfloat16_as_ushort(h0) | ((uint32_t)__bfloat16_as_ushort(h1) << 16);
    ph.y = (uint32_t)__bfloat16_as_ushort(h2) | ((uint32_t)__bfloat16_as_ushort(h3) << 16);
    pl.x = (uint32_t)__bfloat16_as_ushort(l0) | ((uint32_t)__bfloat16_as_ushort(l1) << 16);
    pl.y = (uint32_t)__bfloat16_as_ushort(l2) | ((uint32_t)__bfloat16_as_ushort(l3) << 16);
    *(uint2*)&g_xh[i] = ph;
    *(uint2*)&g_xl[i] = pl;
}
__global__ __launch_bounds__(256) void ctx1_kernel(
    const float* __restrict__ context, const float* __restrict__ cg_w1,
    const float* __restrict__ cg_b1)
{
    __shared__ float cr[8][Cdim];
    const int tid = threadIdx.x;
    const int r0 = blockIdx.y * 8;
    const int row = tid >> 5;
    const int c0 = blockIdx.x * 128 + (tid & 31) * 4;
    for (int i = tid; i < 8 * Cdim; i += 256)
        cr[i >> 6][i & 63] = context[(r0 + (i >> 6)) * Cdim + (i & 63)];
    __syncthreads();
    float4 acc = make_float4(0.f, 0.f, 0.f, 0.f);
#pragma unroll 4
    for (int k = 0; k < Cdim; k++) {
        float4 w = *(const float4*)&cg_w1[k * Hdim + c0];
        float a = cr[row][k];
        acc.x += a * w.x; acc.y += a * w.y;
        acc.z += a * w.z; acc.w += a * w.w;
    }
    float4 bb = *(const float4*)&cg_b1[c0];
    float4 o;
    o.x = fmaxf(acc.x + bb.x, 0.0f);
    o.y = fmaxf(acc.y + bb.y, 0.0f);
    o.z = fmaxf(acc.z + bb.z, 0.0f);
    o.w = fmaxf(acc.w + bb.w, 0.0f);
    *(float4*)&g_tmp[(r0 + row) * Hdim + c0] = o;
}
__global__ __launch_bounds__(256) void ctx2_kernel(
    const float* __restrict__ cg_w2, const float* __restrict__ cg_b2)
{
    __shared__ float tr[16][Hdim];
    const int tid = threadIdx.x;
    const int r0 = blockIdx.y * 16;
    const int c0 = blockIdx.x * 128 + (tid & 63) * 2;
    const int rg = tid >> 6;
    for (int i = tid; i < 16 * Hdim; i += 256)
        tr[i >> 9][i & 511] = g_tmp[(r0 + (i >> 9)) * Hdim + (i & 511)];
    __syncthreads();
    float acc[4][2];
#pragma unroll
    for (int i = 0; i < 4; i++) { acc[i][0] = 0.0f; acc[i][1] = 0.0f; }
#pragma unroll 4
    for (int k = 0; k < Hdim; k++) {
        float2 w = *(const float2*)&cg_w2[k * 1536 + c0];
#pragma unroll
        for (int i = 0; i < 4; i++) {
            float a = tr[rg + 4 * i][k];
            acc[i][0] += a * w.x;
            acc[i][1] += a * w.y;
        }
    }
    float2 bb = *(const float2*)&cg_b2[c0];
#pragma unroll
    for (int i = 0; i < 4; i++) {
        int r = r0 + rg + 4 * i;
        g_ctx[r * 1536 + c0]     = 1.0f / (1.0f + expf(-(acc[i][0] + bb.x)));
        g_ctx[r * 1536 + c0 + 1] = 1.0f / (1.0f + expf(-(acc[i][1] + bb.y)));
    }
}

// ------------------- persistent LSTM: 128 steps, W resident ------------------
// grid (32, 4) = 128 CTAs (1/SM, all resident), 256 threads = 8 warps (4Mx2N).
// group barrier over the 32 CTAs sharing blockIdx.y (the h dependency closure).
__global__ __launch_bounds__(256) void lstm_persist()
{
    extern __shared__ char smem[];
    const uint32_t sb = smem_u32(smem);
    const int tid = threadIdx.x;
    const int wid = tid >> 5, lane = tid & 31;
    const int wm = wid & 3, wn = wid >> 2;
    const int gID = lane >> 2, tid4 = lane & 3;
    const int bx = blockIdx.x, by = blockIdx.y;
    const int n0 = bx * 64;
    const int hcol0 = bx * 16;
    const int b0 = by * 64;

    __shared__ int s_base;
    if (tid == 0) s_base = g_flgG[by];

    // ---- load W tile (hi+lo) into smem via cp.async: one group ----
#pragma unroll 1
    for (int half = 0; half < 2; half++) {
#pragma unroll 1
        for (int i = 0; i < 20; i++) {
            int idx = i * 256 + tid;          // 0..5119
            int r = idx / 80, q = idx - r * 80;
            cp16(sb + half * WHALF + r * WROWB + q * 16,
                 (half ? g_Wl : g_Wh) + (size_t)(n0 + r) * KTOT + q * 8);
        }
    }
    CP_COMMIT();

    // ---- ctx slice + bias into smem (direct stores) ----
    float* sctx = (float*)(smem + CTXOFF);   // [64][48]: m*48 + g*16 + hcl
    for (int i = tid; i < 64 * 48; i += 256) {
        int m = i / 48, rem = i - m * 48;
        int g = rem >> 4, hcl = rem & 15;
        sctx[i] = g_ctx[(size_t)(b0 + m) * 1536 + g * 512 + hcol0 + hcl];
    }
    if (tid < 64) ((float*)(smem + BIASOFF))[tid] = g_bsum[n0 + tid];
    __syncthreads();
    const int base = s_base;

    // cell state in registers (epilogue mapping is step-invariant)
    float c_reg[4] = {0.f, 0.f, 0.f, 0.f};

    const uint32_t aOff = (uint32_t)((wm * 16 + (lane & 15)) * AROWB + ((lane >> 4) * 16));
    const uint32_t bOffW = (uint32_t)((wn * 32 + ((lane >> 4) & 1) * 8 + (lane & 7)) * WROWB
                                      + (((lane >> 3) & 1) * 16));
    const float* biassm = (const float*)(smem + BIASOFF);

#pragma unroll 1
    for (int t = 0; t < Slen; t++) {
        const __nv_bfloat16* __restrict__ hh = g_hh[t & 1];
        const __nv_bfloat16* __restrict__ hl = g_hl[t & 1];
        __nv_bfloat16* __restrict__ ohh = g_hh[(t + 1) & 1];
        __nv_bfloat16* __restrict__ ohl = g_hl[(t + 1) & 1];

        float acc[4][4];
#pragma unroll
        for (int j = 0; j < 4; j++)
#pragma unroll
            for (int r = 0; r < 4; r++) acc[j][r] = 0.0f;

        // A-chunk copy: s = pipeline slot, kc = (s<2)? x-chunk : h-chunk
        auto copyA = [&](int s) {
            const int kc = (s < 2) ? 8 + s : s - 2;
            const uint32_t abase = sb + AOFF + (uint32_t)(s & 1) * ABUF;
#pragma unroll
            for (int half = 0; half < 2; half++) {
#pragma unroll
                for (int i = 0; i < 2; i++) {
                    int idx = i * 256 + tid, r = idx >> 3, q = idx & 7;
                    uint32_t dst = abase + half * AHALF + r * AROWB + q * 16;
                    if (kc < 8) {
                        const __nv_bfloat16* src = half ? hl : hh;
                        cp16(dst, src + (size_t)(b0 + r) * Hdim + kc * 64 + q * 8);
                    } else {
                        const __nv_bfloat16* src = half ? g_xl : g_xh;
                        cp16(dst, src + ((size_t)(b0 + r) * Slen + t) * Fdim + (kc - 8) * 64 + q * 8);
                    }
                }
            }
        };

        auto computec = [&](int s) {
            const int kc = (s < 2) ? 8 + s : s - 2;
            const uint32_t aAddr = sb + AOFF + (uint32_t)(s & 1) * ABUF + aOff;
            const uint32_t bAddr = sb + bOffW + (uint32_t)kc * 128;
#pragma unroll
            for (int ks = 0; ks < 4; ks++) {
                const uint32_t kb = ks * 32;
                uint32_t aH[4], aL[4];
                ldsm_x4(aAddr + kb, aH);
                ldsm_x4(aAddr + kb + AHALF, aL);
#pragma unroll
                for (int p = 0; p < 2; p++) {
                    uint32_t bh[4], bl[4];
                    ldsm_x4(bAddr + p * (16 * WROWB) + kb, bh);
                    ldsm_x4(bAddr + p * (16 * WROWB) + kb + WHALF, bl);
                    mma16816(acc[p * 2 + 0], aH, bh + 0);
                    mma16816(acc[p * 2 + 0], aH, bl + 0);
                    mma16816(acc[p * 2 + 0], aL, bh + 0);
                    mma16816(acc[p * 2 + 1], aH, bh + 2);
                    mma16816(acc[p * 2 + 1], aH, bl + 2);
                    mma16816(acc[p * 2 + 1], aL, bh + 2);
                }
            }
        };

        // x chunks first: copy + compute while (possibly) waiting on the barrier
        copyA(0); CP_COMMIT();
        copyA(1); CP_COMMIT();
        CP_WAIT(1); __syncthreads(); computec(0);   // also completes the W group at t=0
        CP_WAIT(0); __syncthreads(); computec(1);

        // wait: previous step's h published by the whole by-group
        if (t > 0) {
            if (tid == 0) {
                const int target = base + t;
                while (g_flgG[by] < target) {
                    asm volatile("nanosleep.u32 64;");
                }
                __threadfence();
            }
            __syncthreads();
        }

        copyA(2); CP_COMMIT();
#pragma unroll 1
        for (int s = 2; s < NCH; s++) {
            CP_WAIT(0);
            __syncthreads();
            if (s + 1 < NCH) { copyA(s + 1); CP_COMMIT(); }
            computec(s);
        }

        // ---- epilogue: acc -> Csm (buf0; last compute read buf1) ----
        float* Csm = (float*)(smem + AOFF);
#pragma unroll
        for (int j = 0; j < 4; j++) {
            int n = wn * 32 + j * 8 + tid4 * 2;
            int m0r = wm * 16 + gID;
            *(float2*)&Csm[m0r * CST + n]       = make_float2(acc[j][0], acc[j][1]);
            *(float2*)&Csm[(m0r + 8) * CST + n] = make_float2(acc[j][2], acc[j][3]);
        }
        __syncthreads();
#pragma unroll
        for (int it = 0; it < 4; it++) {
            int idx = it * 256 + tid;
            int m = idx >> 4, hcl = idx & 15;
            float4 gv = *(float4*)&Csm[m * CST + hcl * 4];
            float4 bb = *(const float4*)&biassm[hcl * 4];
            int b = b0 + m, hc = hcol0 + hcl;
            const float* cxp = sctx + m * 48;
            float iv = sigf(gv.x + bb.x) * cxp[hcl];
            float fv = sigf(gv.y + bb.y) * cxp[16 + hcl];
            float gg = tanh_fast(gv.z + bb.z);
            float ov = sigf(gv.w + bb.w) * cxp[32 + hcl];
            float cn = fv * c_reg[it] + iv * gg;
            c_reg[it] = cn;
            float hv = ov * tanh_fast(cn);
            __nv_bfloat16 hhi = __float2bfloat16(hv);
            ohh[(size_t)b * Hdim + hc] = hhi;
            ohl[(size_t)b * Hdim + hc] = __float2bfloat16(hv - __bfloat162float(hhi));
        }
        __threadfence();
        __syncthreads();
        // arrive: publish h for epoch t+1 (group scope)
        if (tid == 0) {
            if (atomicAdd(&g_cntG[by], 1) == 31) {
                atomicExch(&g_cntG[by], 0);
                __threadfence();
                g_flgG[by] = base + t + 1;
            }
        }
    }
}

// ------------------------- VAE head -------------------------
__global__ __launch_bounds__(128) void head_kernel(
    const float* __restrict__ eps,
    const float* __restrict__ mu_w, const float* __restrict__ mu_b,
    const float* __restrict__ lv_w, const float* __restrict__ lv_b,
    const float* __restrict__ dec_w1, const float* __restrict__ dec_b1,
    const float* __restrict__ dec_w2, const float* __restrict__ dec_b2,
    float* __restrict__ out)
{
    __shared__ float hrow[Hdim];
    __shared__ float zv[Ldim];
    __shared__ float d1[Hdim];
    int b = blockIdx.x;

    for (int k = threadIdx.x; k < Hdim; k += 128)
        hrow[k] = __bfloat162float(g_hh[0][(size_t)b * Hdim + k]) +
                  __bfloat162float(g_hl[0][(size_t)b * Hdim + k]);
    __syncthreads();

    if (threadIdx.x < Ldim) {
        int j = threadIdx.x;
        float m = mu_b[j];
        for (int k = 0; k < Hdim; k++) m += hrow[k] * mu_w[k * Ldim + j];
        out[Bsz * Fdim + b * Ldim + j] = m;
        float lv = lv_b[j];
        for (int k = 0; k < Hdim; k++) lv += hrow[k] * lv_w[k * Ldim + j];
        out[Bsz * Fdim + Bsz * Ldim + b * Ldim + j] = lv;
        zv[j] = m + eps[b * Ldim + j] * expf(0.5f * lv);
    }
    __syncthreads();

    for (int n = threadIdx.x; n < Hdim; n += 128) {
        float s = dec_b1[n];
#pragma unroll
        for (int k = 0; k < Ldim; k++) s += zv[k] * dec_w1[k * Hdim + n];
        d1[n] = fmaxf(s, 0.0f);
    }
    __syncthreads();
    {
        int n = threadIdx.x;
        float s = dec_b2[n];
        for (int k = 0; k < Hdim; k++) s += d1[k] * dec_w2[k * Fdim + n];
        out[(size_t)b * Fdim + n] = s;
    }
}

// ---------------------------------------------------------------------------
extern "C" void kernel_launch(void* const* d_in, const int* in_sizes, int n_in,
                              void* d_out, int out_size)
{
    const float* x       = (const float*)d_in[0];
    const float* context = (const float*)d_in[1];
    const float* eps     = (const float*)d_in[2];
    const float* W_ih    = (const float*)d_in[3];
    const float* b_ih    = (const float*)d_in[4];
    const float* W_hh    = (const float*)d_in[5];
    const float* b_hh    = (const float*)d_in[6];
    const float* cg_w1   = (const float*)d_in[7];
    const float* cg_b1   = (const float*)d_in[8];
    const float* cg_w2   = (const float*)d_in[9];
    const float* cg_b2   = (const float*)d_in[10];
    const float* mu_w    = (const float*)d_in[11];
    const float* mu_b    = (const float*)d_in[12];
    const float* lv_w    = (const float*)d_in[13];
    const float* lv_b    = (const float*)d_in[14];
    const float* dec_w1  = (const float*)d_in[15];
    const float* dec_b1  = (const float*)d_in[16];
    const float* dec_w2  = (const float*)d_in[17];
    const float* dec_b2  = (const float*)d_in[18];
    float* out = (float*)d_out;

    cudaFuncSetAttribute(lstm_persist, cudaFuncAttributeMaxDynamicSharedMemorySize,
                         SMEM_PERSIST);

    prep_kernel<<<(Bsz * Hdim + 255) / 256, 256>>>(b_ih, b_hh);
    split_w_kernel<<<(G4 * KTOT + 255) / 256, 256>>>(W_ih, W_hh);
    split_x_kernel<<<(Bsz * Slen * Fdim / 4 + 255) / 256, 256>>>(x);
    ctx1_kernel<<<dim3(4, 32), 256>>>(context, cg_w1, cg_b1);
    ctx2_kernel<<<dim3(12, 16), 256>>>(cg_w2, cg_b2);

    lstm_persist<<<dim3(32, 4), 256, SMEM_PERSIST>>>();

    head_kernel<<<Bsz, 128>>>(eps, mu_w, mu_b, lv_w, lv_b,
                              dec_w1, dec_b1, dec_w2, dec_b2, out);
}